// round 10
// baseline (speedup 1.0000x reference)
#include <cuda_runtime.h>
#include <math.h>

#define E    384
#define EE   (E * E)           // 147456 columns
#define TC   32                // columns per block (one warp-width)
#define NBLK (EE / TC)         // 4608 blocks
#define RG   16                // row groups (= warps per block)
#define KPT  (E / RG)          // 24 rows per thread, register-resident
#define THREADS (TC * RG)      // 512

// Order-preserving uint staging for per-row max of (t2 - lse2), log2 domain.
// Zero at module load; gm_fin re-zeros after each read (graph-replay safe).
__device__ unsigned g_stage[E];

__device__ __forceinline__ unsigned fkey(float f) {
    unsigned u = __float_as_uint(f);
    return (u & 0x80000000u) ? ~u : (u | 0x80000000u);
}
__device__ __forceinline__ float funkey(unsigned k) {
    return __uint_as_float((k & 0x80000000u) ? (k ^ 0x80000000u) : ~k);
}

__global__ void __launch_bounds__(THREADS, 2)
gm_main(const float* __restrict__ x,
        const float* __restrict__ kern,
        const float* __restrict__ bias,
        const float* __restrict__ space)
{
    __shared__ float x_s[E];    // x[k] (plain, for dval)
    __shared__ float x2_s[E];   // x[k] * log2(e)  (hot-loop multiplier)
    __shared__ float red[RG][TC];            // cross-warp column-sum reduction
    __shared__ float tr[RG][KPT][TC + 1];    // warp-private transpose tiles

    const int tid = threadIdx.x;
    const int cid = tid & 31;       // lane = column within tile
    const int rg  = tid >> 5;       // warp = row group
    const int k0  = rg * KPT;

    const int c = blockIdx.x * TC + cid;   // global column
    const int l = c % E;                   // kron diag index
    const int j = c / E;

    const float LOG2E = 1.44269504088896340736f;
    if (tid < E) {
        float xv = x[tid];
        x_s[tid]  = xv;
        x2_s[tid] = xv * LOG2E;
    }
    __syncthreads();

    const float INV_SQRT2 = 0.70710678118654752440f;
    // Diagonal kernel term: only live where row k == l; owned by one warp.
    float dval = 0.0f;
    if (l >= k0 && l < k0 + KPT)
        dval = kern[(unsigned)l * (unsigned)EE + (unsigned)c] * x_s[j] * INV_SQRT2;

    // Pass A: stream space+bias, build t2 = t*log2e in registers, accumulate
    // exp2-sum. |t| <= ~1 for this layer, so no max-shift is needed.
    float v[KPT];
    float s_local = 0.0f;
    const unsigned base = (unsigned)k0 * (unsigned)EE + (unsigned)c;
    #pragma unroll
    for (int kk = 0; kk < KPT; ++kk) {
        const int k = k0 + kk;
        const unsigned idx = base + (unsigned)kk * (unsigned)EE;
        float t = space[idx] + bias[idx];
        if (k == l) t += dval;
        t *= x2_s[k];                 // carries the log2e factor
        v[kk] = t;
        s_local += exp2f(t);          // bare MUFU.EX2, no pre-FMUL
    }

    // Column exp2-sum across the 16 row-group warps -> log2-sum-exp2.
    red[rg][cid] = s_local;
    __syncthreads();
    float s_c;
    {   // pairwise tree: dependency depth 4 instead of 16
        float a0 = red[0][cid] + red[1][cid];
        float a1 = red[2][cid] + red[3][cid];
        float a2 = red[4][cid] + red[5][cid];
        float a3 = red[6][cid] + red[7][cid];
        float a4 = red[8][cid] + red[9][cid];
        float a5 = red[10][cid] + red[11][cid];
        float a6 = red[12][cid] + red[13][cid];
        float a7 = red[14][cid] + red[15][cid];
        s_c = ((a0 + a1) + (a2 + a3)) + ((a4 + a5) + (a6 + a7));
    }
    const float lse2 = __log2f(s_c);

    // Pass C (warp-local): transpose (t2 - lse2) through smem, then
    // lanes 0..23 each take the max of one row across 32 columns.
    #pragma unroll
    for (int kk = 0; kk < KPT; ++kk)
        tr[rg][kk][cid] = v[kk] - lse2;
    __syncwarp();
    if (cid < KPT) {
        float best = tr[rg][cid][0];
        #pragma unroll
        for (int cc = 1; cc < TC; ++cc)
            best = fmaxf(best, tr[rg][cid][cc]);
        atomicMax(&g_stage[k0 + cid], fkey(best));   // REDG, spread addrs
    }
}

// out[k] = exp2(max in log2 domain); re-zero staging for the next replay.
__global__ void gm_fin(float* __restrict__ out) {
    const int k = threadIdx.x;
    out[k] = exp2f(funkey(g_stage[k]));
    g_stage[k] = 0u;
}

extern "C" void kernel_launch(void* const* d_in, const int* in_sizes, int n_in,
                              void* d_out, int out_size)
{
    const float* x     = (const float*)d_in[0];
    const float* kern  = (const float*)d_in[1];
    const float* bias  = (const float*)d_in[2];
    const float* space = (const float*)d_in[3];
    float* out = (float*)d_out;

    gm_main<<<NBLK, THREADS>>>(x, kern, bias, space);
    gm_fin<<<1, E>>>(out);
}